// round 1
// baseline (speedup 1.0000x reference)
#include <cuda_runtime.h>
#include <math.h>

#define IN_DIM   512
#define HID      512
#define GRID1    512
#define BLK1     256   // 256 threads * float2 = 512 columns

// Per-block partial column sums (deterministic, no atomics).
__device__ float g_scratch[GRID1 * IN_DIM];

// Kernel 1: partial column sums of X (n_rows x 512), grid-strided rows.
__global__ void __launch_bounds__(BLK1) colsum_kernel(const float* __restrict__ X, int n_rows) {
    const int c2 = threadIdx.x;                 // float2 column index 0..255
    const float2* __restrict__ Xv = (const float2*)X;
    const int stride = GRID1;

    float2 s0 = make_float2(0.f, 0.f);
    float2 s1 = make_float2(0.f, 0.f);
    float2 s2 = make_float2(0.f, 0.f);
    float2 s3 = make_float2(0.f, 0.f);

    int r = blockIdx.x;
    // 4-way unrolled: 4 independent loads in flight per thread
    for (; r + 3 * stride < n_rows; r += 4 * stride) {
        float2 a = Xv[(size_t)(r             ) * (IN_DIM / 2) + c2];
        float2 b = Xv[(size_t)(r +     stride) * (IN_DIM / 2) + c2];
        float2 c = Xv[(size_t)(r + 2 * stride) * (IN_DIM / 2) + c2];
        float2 d = Xv[(size_t)(r + 3 * stride) * (IN_DIM / 2) + c2];
        s0.x += a.x; s0.y += a.y;
        s1.x += b.x; s1.y += b.y;
        s2.x += c.x; s2.y += c.y;
        s3.x += d.x; s3.y += d.y;
    }
    for (; r < n_rows; r += stride) {
        float2 a = Xv[(size_t)r * (IN_DIM / 2) + c2];
        s0.x += a.x; s0.y += a.y;
    }

    float2 s;
    s.x = (s0.x + s1.x) + (s2.x + s3.x);
    s.y = (s0.y + s1.y) + (s2.y + s3.y);
    ((float2*)g_scratch)[(size_t)blockIdx.x * (IN_DIM / 2) + c2] = s;
}

// Kernel 2: every block reduces scratch -> agg (L2-resident), then computes
// 32 outputs of h via warp-per-output dot products. grid = HID/32 = 16.
__global__ void __launch_bounds__(512) gru_finalize_kernel(
    const float* __restrict__ W_ih,
    const float* __restrict__ b_ih,
    const float* __restrict__ b_hh,
    float* __restrict__ out,
    float inv_n)
{
    __shared__ float agg[IN_DIM];
    const int t = threadIdx.x;

    // Phase A: reduce GRID1 partials for column t (coalesced across threads)
    float s = 0.f;
    #pragma unroll 8
    for (int b = 0; b < GRID1; b++)
        s += g_scratch[b * IN_DIM + t];
    agg[t] = s * inv_n;
    __syncthreads();

    // Phase B: matvec + gates. 16 warps, 2 outputs each -> 32 outputs/block.
    const int warp = t >> 5;
    const int lane = t & 31;
    const float4* __restrict__ aggv = (const float4*)agg;

    #pragma unroll
    for (int k = 0; k < 2; k++) {
        const int i = blockIdx.x * 32 + warp * 2 + k;   // output index 0..511

        float acc[3];
        #pragma unroll
        for (int g = 0; g < 3; g++) {
            const float4* __restrict__ row =
                (const float4*)(W_ih + (size_t)(g * HID + i) * IN_DIM);
            float a = 0.f;
            #pragma unroll
            for (int u = 0; u < 4; u++) {
                float4 w = row[lane + u * 32];
                float4 x = aggv[lane + u * 32];
                a += w.x * x.x + w.y * x.y + w.z * x.z + w.w * x.w;
            }
            // warp reduction
            #pragma unroll
            for (int off = 16; off; off >>= 1)
                a += __shfl_xor_sync(0xFFFFFFFFu, a, off);
            acc[g] = a;
        }

        if (lane == 0) {
            // gi = W_ih @ agg + b_ih ;  gh = b_hh (since h = 0)
            float gi_r = acc[0] + b_ih[i];
            float gi_z = acc[1] + b_ih[HID + i];
            float gi_n = acc[2] + b_ih[2 * HID + i];
            float r = 1.f / (1.f + __expf(-(gi_r + b_hh[i])));
            float z = 1.f / (1.f + __expf(-(gi_z + b_hh[HID + i])));
            float n = tanhf(gi_n + r * b_hh[2 * HID + i]);
            out[i] = (1.f - z) * n;   // + z*h with h=0
        }
    }
}

extern "C" void kernel_launch(void* const* d_in, const int* in_sizes, int n_in,
                              void* d_out, int out_size) {
    const float* parent_states = (const float*)d_in[0];
    const float* weight_ih     = (const float*)d_in[1];
    // d_in[2] = weight_hh : unused (h = 0 -> W_hh @ h = 0)
    const float* bias_ih       = (const float*)d_in[3];
    const float* bias_hh       = (const float*)d_in[4];
    float* out = (float*)d_out;

    const int n_rows = in_sizes[0] / IN_DIM;
    const float inv_n = 1.0f / (float)n_rows;

    colsum_kernel<<<GRID1, BLK1>>>(parent_states, n_rows);
    gru_finalize_kernel<<<HID / 32, 512>>>(weight_ih, bias_ih, bias_hh, out, inv_n);
}

// round 2
// speedup vs baseline: 1.1746x; 1.1746x over previous
#include <cuda_runtime.h>
#include <math.h>

#define IN_DIM   512
#define HID      512
#define GRID1    512
#define BLK1     256   // 256 threads * float2 = 512 columns

// Per-block partial column sums (deterministic, no atomics).
__device__ float g_scratch[GRID1 * IN_DIM];
__device__ float g_agg[IN_DIM];

// ---------------------------------------------------------------------------
// Kernel 1: partial column sums of X (n_rows x 512), grid-strided rows.
// At HBM roofline (~7.8 TB/s measured) — do not touch.
// ---------------------------------------------------------------------------
__global__ void __launch_bounds__(BLK1) colsum_kernel(const float* __restrict__ X, int n_rows) {
    const int c2 = threadIdx.x;                 // float2 column index 0..255
    const float2* __restrict__ Xv = (const float2*)X;
    const int stride = GRID1;

    float2 s0 = make_float2(0.f, 0.f);
    float2 s1 = make_float2(0.f, 0.f);
    float2 s2 = make_float2(0.f, 0.f);
    float2 s3 = make_float2(0.f, 0.f);

    int r = blockIdx.x;
    for (; r + 3 * stride < n_rows; r += 4 * stride) {
        float2 a = Xv[(size_t)(r             ) * (IN_DIM / 2) + c2];
        float2 b = Xv[(size_t)(r +     stride) * (IN_DIM / 2) + c2];
        float2 c = Xv[(size_t)(r + 2 * stride) * (IN_DIM / 2) + c2];
        float2 d = Xv[(size_t)(r + 3 * stride) * (IN_DIM / 2) + c2];
        s0.x += a.x; s0.y += a.y;
        s1.x += b.x; s1.y += b.y;
        s2.x += c.x; s2.y += c.y;
        s3.x += d.x; s3.y += d.y;
    }
    for (; r < n_rows; r += stride) {
        float2 a = Xv[(size_t)r * (IN_DIM / 2) + c2];
        s0.x += a.x; s0.y += a.y;
    }

    float2 s;
    s.x = (s0.x + s1.x) + (s2.x + s3.x);
    s.y = (s0.y + s1.y) + (s2.y + s3.y);
    ((float2*)g_scratch)[(size_t)blockIdx.x * (IN_DIM / 2) + c2] = s;
}

// ---------------------------------------------------------------------------
// Kernel 2: reduce 512 partial rows -> agg (512 floats).
// grid=8, block=256. Block b owns columns [b*64, b*64+64).
// Thread layout: tx = t&63 (column), ty = t>>6 (0..3, partial-row phase).
// Loads are 64-float (256B) coalesced per (ty, row) step. 128 serial loads
// per thread, 8-way unrolled for MLP.
// ---------------------------------------------------------------------------
__global__ void __launch_bounds__(256) reduce_kernel(float inv_n) {
    __shared__ float part[4][64];
    const int t  = threadIdx.x;
    const int tx = t & 63;
    const int ty = t >> 6;
    const int col = blockIdx.x * 64 + tx;

    float s = 0.f;
    #pragma unroll 8
    for (int p = ty; p < GRID1; p += 4)
        s += g_scratch[p * IN_DIM + col];

    part[ty][tx] = s;
    __syncthreads();
    if (ty == 0) {
        float tot = (part[0][tx] + part[1][tx]) + (part[2][tx] + part[3][tx]);
        g_agg[col] = tot * inv_n;
    }
}

// ---------------------------------------------------------------------------
// Kernel 3: gi = W_ih @ agg + b_ih ; gates with gh = b_hh (h = 0).
// grid=64, block=256 (8 warps). One warp per output i; 3 gate dot-products
// of length 512 each, float4 loads + shuffle reduce.
// ---------------------------------------------------------------------------
__global__ void __launch_bounds__(256) gru_matvec_kernel(
    const float* __restrict__ W_ih,
    const float* __restrict__ b_ih,
    const float* __restrict__ b_hh,
    float* __restrict__ out)
{
    __shared__ float agg[IN_DIM];
    const int t = threadIdx.x;
    agg[t]       = g_agg[t];
    agg[t + 256] = g_agg[t + 256];
    __syncthreads();

    const int warp = t >> 5;
    const int lane = t & 31;
    const int i = blockIdx.x * 8 + warp;     // output index 0..511
    const float4* __restrict__ aggv = (const float4*)agg;

    float acc[3];
    #pragma unroll
    for (int g = 0; g < 3; g++) {
        const float4* __restrict__ row =
            (const float4*)(W_ih + (size_t)(g * HID + i) * IN_DIM);
        float a = 0.f;
        #pragma unroll
        for (int u = 0; u < 4; u++) {
            float4 w = row[lane + u * 32];
            float4 x = aggv[lane + u * 32];
            a += w.x * x.x + w.y * x.y + w.z * x.z + w.w * x.w;
        }
        #pragma unroll
        for (int off = 16; off; off >>= 1)
            a += __shfl_xor_sync(0xFFFFFFFFu, a, off);
        acc[g] = a;
    }

    if (lane == 0) {
        float gi_r = acc[0] + b_ih[i];
        float gi_z = acc[1] + b_ih[HID + i];
        float gi_n = acc[2] + b_ih[2 * HID + i];
        float r = 1.f / (1.f + __expf(-(gi_r + b_hh[i])));
        float z = 1.f / (1.f + __expf(-(gi_z + b_hh[HID + i])));
        float n = tanhf(gi_n + r * b_hh[2 * HID + i]);
        out[i] = (1.f - z) * n;   // + z*h with h=0
    }
}

extern "C" void kernel_launch(void* const* d_in, const int* in_sizes, int n_in,
                              void* d_out, int out_size) {
    const float* parent_states = (const float*)d_in[0];
    const float* weight_ih     = (const float*)d_in[1];
    // d_in[2] = weight_hh : unused (h = 0 -> W_hh @ h = 0)
    const float* bias_ih       = (const float*)d_in[3];
    const float* bias_hh       = (const float*)d_in[4];
    float* out = (float*)d_out;

    const int n_rows = in_sizes[0] / IN_DIM;
    const float inv_n = 1.0f / (float)n_rows;

    colsum_kernel<<<GRID1, BLK1>>>(parent_states, n_rows);
    reduce_kernel<<<8, 256>>>(inv_n);
    gru_matvec_kernel<<<64, 256>>>(weight_ih, bias_ih, bias_hh, out);
}

// round 3
// speedup vs baseline: 1.2720x; 1.0829x over previous
#include <cuda_runtime.h>
#include <math.h>

#define IN_DIM   512
#define HID      512
#define GRID1    1024
#define BLK1     128    // 128 threads * float4 = 512 columns

// Per-block partial column sums (deterministic, no atomics). 2 MB.
__device__ float g_scratch[GRID1 * IN_DIM];
__device__ float g_agg[IN_DIM];

// ---------------------------------------------------------------------------
// Kernel 1: partial column sums of X (n_rows x 512).
// 128 threads cover one row via float4; 8-way unrolled grid-stride over rows
// -> 8 independent LDG.128 in flight per thread (512B/thread outstanding).
// ---------------------------------------------------------------------------
__global__ void __launch_bounds__(BLK1) colsum_kernel(const float* __restrict__ X, int n_rows) {
    const int c4 = threadIdx.x;                 // float4 column index 0..127
    const float4* __restrict__ Xv = (const float4*)X;
    const int S = GRID1;

    float4 acc0 = make_float4(0.f, 0.f, 0.f, 0.f);
    float4 acc1 = make_float4(0.f, 0.f, 0.f, 0.f);
    float4 acc2 = make_float4(0.f, 0.f, 0.f, 0.f);
    float4 acc3 = make_float4(0.f, 0.f, 0.f, 0.f);

    int r = blockIdx.x;
    for (; r + 7 * S < n_rows; r += 8 * S) {
        // 8 independent loads issued back-to-back
        float4 v0 = Xv[(size_t)(r        ) * 128 + c4];
        float4 v1 = Xv[(size_t)(r + 1 * S) * 128 + c4];
        float4 v2 = Xv[(size_t)(r + 2 * S) * 128 + c4];
        float4 v3 = Xv[(size_t)(r + 3 * S) * 128 + c4];
        float4 v4 = Xv[(size_t)(r + 4 * S) * 128 + c4];
        float4 v5 = Xv[(size_t)(r + 5 * S) * 128 + c4];
        float4 v6 = Xv[(size_t)(r + 6 * S) * 128 + c4];
        float4 v7 = Xv[(size_t)(r + 7 * S) * 128 + c4];
        acc0.x += v0.x; acc0.y += v0.y; acc0.z += v0.z; acc0.w += v0.w;
        acc1.x += v1.x; acc1.y += v1.y; acc1.z += v1.z; acc1.w += v1.w;
        acc2.x += v2.x; acc2.y += v2.y; acc2.z += v2.z; acc2.w += v2.w;
        acc3.x += v3.x; acc3.y += v3.y; acc3.z += v3.z; acc3.w += v3.w;
        acc0.x += v4.x; acc0.y += v4.y; acc0.z += v4.z; acc0.w += v4.w;
        acc1.x += v5.x; acc1.y += v5.y; acc1.z += v5.z; acc1.w += v5.w;
        acc2.x += v6.x; acc2.y += v6.y; acc2.z += v6.z; acc2.w += v6.w;
        acc3.x += v7.x; acc3.y += v7.y; acc3.z += v7.z; acc3.w += v7.w;
    }
    for (; r < n_rows; r += S) {
        float4 v = Xv[(size_t)r * 128 + c4];
        acc0.x += v.x; acc0.y += v.y; acc0.z += v.z; acc0.w += v.w;
    }

    float4 s;
    s.x = (acc0.x + acc1.x) + (acc2.x + acc3.x);
    s.y = (acc0.y + acc1.y) + (acc2.y + acc3.y);
    s.z = (acc0.z + acc1.z) + (acc2.z + acc3.z);
    s.w = (acc0.w + acc1.w) + (acc2.w + acc3.w);
    ((float4*)g_scratch)[(size_t)blockIdx.x * 128 + c4] = s;
}

// ---------------------------------------------------------------------------
// Kernel 2: reduce 1024 partial rows -> agg (512 floats). Scratch is
// L2-resident (written at the tail of colsum). grid=32, block=256.
// Block b owns columns [b*16, b*16+16); ty in [0,16) strides partial rows.
// 64 serial loads per thread, 8-way unrolled.
// ---------------------------------------------------------------------------
__global__ void __launch_bounds__(256) reduce_kernel(float inv_n) {
    __shared__ float part[16][16];
    const int t  = threadIdx.x;
    const int tx = t & 15;
    const int ty = t >> 4;
    const int col = blockIdx.x * 16 + tx;

    float s = 0.f;
    #pragma unroll 8
    for (int p = ty; p < GRID1; p += 16)
        s += g_scratch[p * IN_DIM + col];

    part[ty][tx] = s;
    __syncthreads();
    if (ty == 0) {
        float tot = 0.f;
        #pragma unroll
        for (int k = 0; k < 16; k++)
            tot += part[k][tx];
        g_agg[col] = tot * inv_n;
    }
}

// ---------------------------------------------------------------------------
// Kernel 3: gi = W_ih @ agg + b_ih ; gates with gh = b_hh (h = 0).
// grid=128, block=128 (4 warps). One warp per output i.
// ---------------------------------------------------------------------------
__global__ void __launch_bounds__(128) gru_matvec_kernel(
    const float* __restrict__ W_ih,
    const float* __restrict__ b_ih,
    const float* __restrict__ b_hh,
    float* __restrict__ out)
{
    __shared__ float agg[IN_DIM];
    const int t = threadIdx.x;
    #pragma unroll
    for (int k = 0; k < 4; k++)
        agg[t + k * 128] = g_agg[t + k * 128];
    __syncthreads();

    const int warp = t >> 5;
    const int lane = t & 31;
    const int i = blockIdx.x * 4 + warp;     // output index 0..511
    const float4* __restrict__ aggv = (const float4*)agg;

    float acc[3];
    #pragma unroll
    for (int g = 0; g < 3; g++) {
        const float4* __restrict__ row =
            (const float4*)(W_ih + (size_t)(g * HID + i) * IN_DIM);
        float a = 0.f;
        #pragma unroll
        for (int u = 0; u < 4; u++) {
            float4 w = row[lane + u * 32];
            float4 x = aggv[lane + u * 32];
            a += w.x * x.x + w.y * x.y + w.z * x.z + w.w * x.w;
        }
        #pragma unroll
        for (int off = 16; off; off >>= 1)
            a += __shfl_xor_sync(0xFFFFFFFFu, a, off);
        acc[g] = a;
    }

    if (lane == 0) {
        float gi_r = acc[0] + b_ih[i];
        float gi_z = acc[1] + b_ih[HID + i];
        float gi_n = acc[2] + b_ih[2 * HID + i];
        float r = 1.f / (1.f + __expf(-(gi_r + b_hh[i])));
        float z = 1.f / (1.f + __expf(-(gi_z + b_hh[HID + i])));
        float n = tanhf(gi_n + r * b_hh[2 * HID + i]);
        out[i] = (1.f - z) * n;   // + z*h with h=0
    }
}

extern "C" void kernel_launch(void* const* d_in, const int* in_sizes, int n_in,
                              void* d_out, int out_size) {
    const float* parent_states = (const float*)d_in[0];
    const float* weight_ih     = (const float*)d_in[1];
    // d_in[2] = weight_hh : unused (h = 0 -> W_hh @ h = 0)
    const float* bias_ih       = (const float*)d_in[3];
    const float* bias_hh       = (const float*)d_in[4];
    float* out = (float*)d_out;

    const int n_rows = in_sizes[0] / IN_DIM;
    const float inv_n = 1.0f / (float)n_rows;

    colsum_kernel<<<GRID1, BLK1>>>(parent_states, n_rows);
    reduce_kernel<<<32, 256>>>(inv_n);
    gru_matvec_kernel<<<128, 128>>>(weight_ih, bias_ih, bias_hh, out);
}